// round 7
// baseline (speedup 1.0000x reference)
#include <cuda_runtime.h>
#include <math.h>

#define N_LEVELS 16
#define HASHMAP_SIZE 32768
#define HASH_MASK 32767u
#define NPTS 524288
#define P1 2654435761u
#define P2 805459861u
#define MBITS 6                       // morton bits per dim
#define NBUCK (1 << (3 * MBITS))      // 262144 buckets

// Materialized per-level tables: [16][32768] x float2 (4 MB), 16B-aligned.
__device__ __align__(16) float2 g_tables[N_LEVELS * HASHMAP_SIZE];

// Counting-sort scratch
__device__ __align__(16) unsigned g_hist[NBUCK];
__device__ __align__(16) unsigned g_offs[NBUCK];
__device__ unsigned g_blk[256];
__device__ unsigned g_bucket[NPTS];
__device__ float4   g_sx[NPTS];       // sorted normalized coords
__device__ int      g_sidx[NPTS];     // sorted slot -> original point index

struct ResParams { float res[N_LEVELS]; };

// ---------------------------------------------------------------------------
// Kernel 1: tables[l][s][:] = A[l][s][0:4] @ B[l][0:4][0:2]
// ---------------------------------------------------------------------------
__global__ void __launch_bounds__(256) build_tables_kernel(
    const float* __restrict__ A, const float* __restrict__ B) {
    int idx = blockIdx.x * blockDim.x + threadIdx.x;
    int l = idx >> 15;
    float4 a = __ldg(reinterpret_cast<const float4*>(A) + idx);
    const float* b = B + l * 8;
    float f0 = a.x * b[0];
    f0 = fmaf(a.y, b[2], f0);
    f0 = fmaf(a.z, b[4], f0);
    f0 = fmaf(a.w, b[6], f0);
    float f1 = a.x * b[1];
    f1 = fmaf(a.y, b[3], f1);
    f1 = fmaf(a.z, b[5], f1);
    f1 = fmaf(a.w, b[7], f1);
    g_tables[idx] = make_float2(f0, f1);
}

// ---------------------------------------------------------------------------
// Morton helpers + counting sort
// ---------------------------------------------------------------------------
__device__ __forceinline__ unsigned part1by2(unsigned v) {
    v &= 0x3FFu;
    v = (v | (v << 16)) & 0x030000FFu;
    v = (v | (v << 8))  & 0x0300F00Fu;
    v = (v | (v << 4))  & 0x030C30C3u;
    v = (v | (v << 2))  & 0x09249249u;
    return v;
}

__global__ void __launch_bounds__(256) zero_hist_kernel() {
    int i = blockIdx.x * blockDim.x + threadIdx.x;
    reinterpret_cast<uint4*>(g_hist)[i] = make_uint4(0u, 0u, 0u, 0u);
}

__global__ void __launch_bounds__(256) hist_kernel(const float* __restrict__ x) {
    int n = blockIdx.x * blockDim.x + threadIdx.x;
    float xn0 = (__ldg(&x[3 * n + 0]) + 1.0f) * 0.5f;
    float xn1 = (__ldg(&x[3 * n + 1]) + 1.0f) * 0.5f;
    float xn2 = (__ldg(&x[3 * n + 2]) + 1.0f) * 0.5f;
    int cx = min(max((int)(xn0 * 64.0f), 0), 63);
    int cy = min(max((int)(xn1 * 64.0f), 0), 63);
    int cz = min(max((int)(xn2 * 64.0f), 0), 63);
    unsigned code = part1by2((unsigned)cx)
                  | (part1by2((unsigned)cy) << 1)
                  | (part1by2((unsigned)cz) << 2);
    g_bucket[n] = code;
    atomicAdd(&g_hist[code], 1u);
}

__global__ void __launch_bounds__(256) scanA_kernel() {
    __shared__ unsigned s[256];
    int t = threadIdx.x;
    int base = blockIdx.x * 1024 + t * 4;
    uint4 v = reinterpret_cast<const uint4*>(g_hist)[base >> 2];
    unsigned sum = v.x + v.y + v.z + v.w;
    s[t] = sum;
    __syncthreads();
#pragma unroll
    for (int d = 1; d < 256; d <<= 1) {
        unsigned u = (t >= d) ? s[t - d] : 0u;
        __syncthreads();
        s[t] += u;
        __syncthreads();
    }
    unsigned ex = s[t] - sum;
    uint4 o;
    o.x = ex;
    o.y = ex + v.x;
    o.z = o.y + v.y;
    o.w = o.z + v.z;
    reinterpret_cast<uint4*>(g_offs)[base >> 2] = o;
    if (t == 255) g_blk[blockIdx.x] = s[255];
}

__global__ void __launch_bounds__(256) scanB_kernel() {
    __shared__ unsigned s[256];
    int t = threadIdx.x;
    unsigned v = g_blk[t];
    s[t] = v;
    __syncthreads();
#pragma unroll
    for (int d = 1; d < 256; d <<= 1) {
        unsigned u = (t >= d) ? s[t - d] : 0u;
        __syncthreads();
        s[t] += u;
        __syncthreads();
    }
    g_blk[t] = s[t] - v;        // exclusive
}

// scatter with fused block-offset add (scanC folded in)
__global__ void __launch_bounds__(256) scatter_kernel(const float* __restrict__ x) {
    int n = blockIdx.x * blockDim.x + threadIdx.x;
    float xn0 = (__ldg(&x[3 * n + 0]) + 1.0f) * 0.5f;
    float xn1 = (__ldg(&x[3 * n + 1]) + 1.0f) * 0.5f;
    float xn2 = (__ldg(&x[3 * n + 2]) + 1.0f) * 0.5f;
    unsigned code = g_bucket[n];
    unsigned pos = atomicAdd(&g_offs[code], 1u) + __ldg(&g_blk[code >> 10]);
    g_sx[pos] = make_float4(xn0, xn1, xn2, 0.0f);
    g_sidx[pos] = n;
}

// ---------------------------------------------------------------------------
// Encode. Warp-homogeneous halves: warp W handles 32 consecutive sorted
// points at levels [l0, l0+8). Fine levels (>=11) use L1::no_allocate.
// ---------------------------------------------------------------------------
__device__ __forceinline__ float2 lerp2(float2 a, float2 b, float t) {
    return make_float2(fmaf(t, b.x - a.x, a.x),
                       fmaf(t, b.y - a.y, a.y));
}

__device__ __forceinline__ float2 ldg_na2(const float2* p) {
    float2 v;
    asm("ld.global.nc.L1::no_allocate.v2.f32 {%0,%1}, [%2];"
        : "=f"(v.x), "=f"(v.y) : "l"(p));
    return v;
}
__device__ __forceinline__ float4 ldg_na4(const float4* p) {
    float4 v;
    asm("ld.global.nc.L1::no_allocate.v4.f32 {%0,%1,%2,%3}, [%4];"
        : "=f"(v.x), "=f"(v.y), "=f"(v.z), "=f"(v.w) : "l"(p));
    return v;
}

template<int L0>
__device__ __forceinline__ void encode_levels(
    float xn0, float xn1, float xn2, const ResParams& p, float4* o) {
    float2 prev;
#pragma unroll
    for (int k = 0; k < 8; k++) {
        const int l = L0 + k;
        const bool NA = (l >= 11);       // compile-time per unrolled iter

        float r = p.res[l];
        float fx = xn0 * r, fy = xn1 * r, fz = xn2 * r;
        float flx = floorf(fx), fly = floorf(fy), flz = floorf(fz);
        float wx = fx - flx, wy = fy - fly, wz = fz - flz;
        unsigned ix = (unsigned)flx;
        unsigned iy = (unsigned)fly;
        unsigned iz = (unsigned)flz;

        unsigned hy0 = iy * P1;
        unsigned hy1 = hy0 + P1;
        unsigned hz0 = iz * P2;
        unsigned hz1 = hz0 + P2;
        unsigned r00 = hy0 ^ hz0;
        unsigned r10 = hy1 ^ hz0;
        unsigned r01 = hy0 ^ hz1;
        unsigned r11 = hy1 ^ hz1;

        const float2* tab = g_tables + (l << 15);
        float2 a00, b00, a10, b10, a01, b01, a11, b11;

        if ((ix & 1u) == 0u) {
            const float4* tab4 = reinterpret_cast<const float4*>(tab);
#define LOAD_PAIR(RYZ, AV, BV)                                              \
            {                                                               \
                unsigned i0 = (ix ^ (RYZ)) & HASH_MASK;                     \
                float4 q = NA ? ldg_na4(&tab4[i0 >> 1])                     \
                              : __ldg(&tab4[i0 >> 1]);                      \
                float2 qlo = make_float2(q.x, q.y);                         \
                float2 qhi = make_float2(q.z, q.w);                         \
                bool sw = (i0 & 1u) != 0u;                                  \
                AV = sw ? qhi : qlo;                                        \
                BV = sw ? qlo : qhi;                                        \
            }
            LOAD_PAIR(r00, a00, b00)
            LOAD_PAIR(r10, a10, b10)
            LOAD_PAIR(r01, a01, b01)
            LOAD_PAIR(r11, a11, b11)
#undef LOAD_PAIR
        } else {
            unsigned x1 = ix + 1u;
#define LOAD1(IDX) (NA ? ldg_na2(&tab[(IDX) & HASH_MASK])                   \
                       : __ldg(&tab[(IDX) & HASH_MASK]))
            a00 = LOAD1(ix ^ r00);
            b00 = LOAD1(x1 ^ r00);
            a10 = LOAD1(ix ^ r10);
            b10 = LOAD1(x1 ^ r10);
            a01 = LOAD1(ix ^ r01);
            b01 = LOAD1(x1 ^ r01);
            a11 = LOAD1(ix ^ r11);
            b11 = LOAD1(x1 ^ r11);
#undef LOAD1
        }

        float2 m00 = lerp2(a00, b00, wx);
        float2 m10 = lerp2(a10, b10, wx);
        float2 m01 = lerp2(a01, b01, wx);
        float2 m11 = lerp2(a11, b11, wx);
        float2 mm0 = lerp2(m00, m10, wy);
        float2 mm1 = lerp2(m01, m11, wy);
        float2 rr  = lerp2(mm0, mm1, wz);

        if ((k & 1) == 0) {
            prev = rr;
        } else {
            o[k >> 1] = make_float4(prev.x, prev.y, rr.x, rr.y);
        }
    }
}

__global__ void __launch_bounds__(256) encode_kernel(
    float* __restrict__ out, ResParams p) {
    int tid = blockIdx.x * blockDim.x + threadIdx.x;   // 0 .. 2*NPTS-1
    int W    = tid >> 5;
    int lane = tid & 31;
    int half = W & 1;
    int s    = ((W >> 1) << 5) | lane;                 // sorted point slot

    float4 c = g_sx[s];
    int n = g_sidx[s];

    float4* o = reinterpret_cast<float4*>(out + (size_t)n * 32) + (half << 2);
    if (half == 0) encode_levels<0>(c.x, c.y, c.z, p, o);
    else           encode_levels<8>(c.x, c.y, c.z, p, o);
}

// ---------------------------------------------------------------------------
// Launch
// ---------------------------------------------------------------------------
extern "C" void kernel_launch(void* const* d_in, const int* in_sizes, int n_in,
                              void* d_out, int out_size) {
    const float* x = (const float*)d_in[0];        // [524288, 3]
    const float* A = (const float*)d_in[1];        // [16, 32768, 4]
    const float* B = (const float*)d_in[2];        // [16, 4, 2]
    float* out = (float*)d_out;                    // [524288, 32]

    // Replicate numpy's resolution computation bit-exactly.
    ResParams p;
    double b = exp((log(512.0) - log(16.0)) / 15.0);
    for (int l = 0; l < N_LEVELS; l++) {
        double bl;
        if (l == 0)      bl = 1.0;
        else if (l == 1) bl = b;
        else if (l == 2) bl = b * b;
        else             bl = pow(b, (double)l);
        p.res[l] = (float)floor(16.0 * bl);
    }

    build_tables_kernel<<<(N_LEVELS * HASHMAP_SIZE) / 256, 256>>>(A, B);
    zero_hist_kernel<<<NBUCK / 1024, 256>>>();
    hist_kernel<<<NPTS / 256, 256>>>(x);
    scanA_kernel<<<256, 256>>>();
    scanB_kernel<<<1, 256>>>();
    scatter_kernel<<<NPTS / 256, 256>>>(x);
    encode_kernel<<<(2 * NPTS) / 256, 256>>>(out, p);
}

// round 8
// speedup vs baseline: 1.0925x; 1.0925x over previous
#include <cuda_runtime.h>
#include <math.h>

#define N_LEVELS 16
#define HASHMAP_SIZE 32768
#define HASH_MASK 32767u
#define NPTS 524288
#define P1 2654435761u
#define P2 805459861u
#define MBITS 6                       // morton bits per dim
#define NBUCK (1 << (3 * MBITS))      // 262144 buckets

// Materialized per-level tables: [16][32768] x float2 (4 MB), 16B-aligned.
__device__ __align__(16) float2 g_tables[N_LEVELS * HASHMAP_SIZE];

// Counting-sort scratch
__device__ __align__(16) unsigned g_hist[NBUCK];
__device__ __align__(16) unsigned g_offs[NBUCK];
__device__ unsigned g_blk[256];
__device__ unsigned g_bucket[NPTS];
__device__ float4   g_sx[NPTS];       // sorted normalized coords
__device__ int      g_sidx[NPTS];     // sorted slot -> original point index

struct ResParams { float res[N_LEVELS]; };

// ---------------------------------------------------------------------------
// Kernel 1: tables[l][s][:] = A[l][s][0:4] @ B[l][0:4][0:2]
// ---------------------------------------------------------------------------
__global__ void __launch_bounds__(256) build_tables_kernel(
    const float* __restrict__ A, const float* __restrict__ B) {
    int idx = blockIdx.x * blockDim.x + threadIdx.x;
    int l = idx >> 15;
    float4 a = __ldg(reinterpret_cast<const float4*>(A) + idx);
    const float* b = B + l * 8;
    float f0 = a.x * b[0];
    f0 = fmaf(a.y, b[2], f0);
    f0 = fmaf(a.z, b[4], f0);
    f0 = fmaf(a.w, b[6], f0);
    float f1 = a.x * b[1];
    f1 = fmaf(a.y, b[3], f1);
    f1 = fmaf(a.z, b[5], f1);
    f1 = fmaf(a.w, b[7], f1);
    g_tables[idx] = make_float2(f0, f1);
}

// ---------------------------------------------------------------------------
// Morton helpers + counting sort
// ---------------------------------------------------------------------------
__device__ __forceinline__ unsigned part1by2(unsigned v) {
    v &= 0x3FFu;
    v = (v | (v << 16)) & 0x030000FFu;
    v = (v | (v << 8))  & 0x0300F00Fu;
    v = (v | (v << 4))  & 0x030C30C3u;
    v = (v | (v << 2))  & 0x09249249u;
    return v;
}

__global__ void __launch_bounds__(256) zero_hist_kernel() {
    int i = blockIdx.x * blockDim.x + threadIdx.x;
    reinterpret_cast<uint4*>(g_hist)[i] = make_uint4(0u, 0u, 0u, 0u);
}

__global__ void __launch_bounds__(256) hist_kernel(const float* __restrict__ x) {
    int n = blockIdx.x * blockDim.x + threadIdx.x;
    float xn0 = (__ldg(&x[3 * n + 0]) + 1.0f) * 0.5f;
    float xn1 = (__ldg(&x[3 * n + 1]) + 1.0f) * 0.5f;
    float xn2 = (__ldg(&x[3 * n + 2]) + 1.0f) * 0.5f;
    int cx = min(max((int)(xn0 * 64.0f), 0), 63);
    int cy = min(max((int)(xn1 * 64.0f), 0), 63);
    int cz = min(max((int)(xn2 * 64.0f), 0), 63);
    unsigned code = part1by2((unsigned)cx)
                  | (part1by2((unsigned)cy) << 1)
                  | (part1by2((unsigned)cz) << 2);
    g_bucket[n] = code;
    atomicAdd(&g_hist[code], 1u);
}

__global__ void __launch_bounds__(256) scanA_kernel() {
    __shared__ unsigned s[256];
    int t = threadIdx.x;
    int base = blockIdx.x * 1024 + t * 4;
    uint4 v = reinterpret_cast<const uint4*>(g_hist)[base >> 2];
    unsigned sum = v.x + v.y + v.z + v.w;
    s[t] = sum;
    __syncthreads();
#pragma unroll
    for (int d = 1; d < 256; d <<= 1) {
        unsigned u = (t >= d) ? s[t - d] : 0u;
        __syncthreads();
        s[t] += u;
        __syncthreads();
    }
    unsigned ex = s[t] - sum;
    uint4 o;
    o.x = ex;
    o.y = ex + v.x;
    o.z = o.y + v.y;
    o.w = o.z + v.z;
    reinterpret_cast<uint4*>(g_offs)[base >> 2] = o;
    if (t == 255) g_blk[blockIdx.x] = s[255];
}

__global__ void __launch_bounds__(256) scanB_kernel() {
    __shared__ unsigned s[256];
    int t = threadIdx.x;
    unsigned v = g_blk[t];
    s[t] = v;
    __syncthreads();
#pragma unroll
    for (int d = 1; d < 256; d <<= 1) {
        unsigned u = (t >= d) ? s[t - d] : 0u;
        __syncthreads();
        s[t] += u;
        __syncthreads();
    }
    g_blk[t] = s[t] - v;        // exclusive
}

// scatter with fused block-offset add (scanC folded in)
__global__ void __launch_bounds__(256) scatter_kernel(const float* __restrict__ x) {
    int n = blockIdx.x * blockDim.x + threadIdx.x;
    float xn0 = (__ldg(&x[3 * n + 0]) + 1.0f) * 0.5f;
    float xn1 = (__ldg(&x[3 * n + 1]) + 1.0f) * 0.5f;
    float xn2 = (__ldg(&x[3 * n + 2]) + 1.0f) * 0.5f;
    unsigned code = g_bucket[n];
    unsigned pos = atomicAdd(&g_offs[code], 1u) + __ldg(&g_blk[code >> 10]);
    g_sx[pos] = make_float4(xn0, xn1, xn2, 0.0f);
    g_sidx[pos] = n;
}

// ---------------------------------------------------------------------------
// Encode (R6 version): thread = (sorted slot, half of levels), mixed halves
// within a warp. Morton order gives cross-lane L1 line sharing at coarse
// levels; mixed coarse/fine lanes balance load within each warp.
// ---------------------------------------------------------------------------
__device__ __forceinline__ float2 lerp2(float2 a, float2 b, float t) {
    return make_float2(fmaf(t, b.x - a.x, a.x),
                       fmaf(t, b.y - a.y, a.y));
}

__global__ void __launch_bounds__(256) encode_kernel(
    float* __restrict__ out, ResParams p) {
    int tid = blockIdx.x * blockDim.x + threadIdx.x;   // 0 .. 2*NPTS-1
    int s    = tid >> 1;
    int half = tid & 1;
    int l0   = half << 3;

    float4 c = g_sx[s];
    int n = g_sidx[s];
    float xn0 = c.x, xn1 = c.y, xn2 = c.z;

    float4* o = reinterpret_cast<float4*>(out + (size_t)n * 32) + (half << 2);
    float2 prev;

#pragma unroll
    for (int k = 0; k < 8; k++) {
        int l = l0 + k;
        float r = p.res[l];
        float fx = xn0 * r, fy = xn1 * r, fz = xn2 * r;
        float flx = floorf(fx), fly = floorf(fy), flz = floorf(fz);
        float wx = fx - flx, wy = fy - fly, wz = fz - flz;
        unsigned ix = (unsigned)flx;
        unsigned iy = (unsigned)fly;
        unsigned iz = (unsigned)flz;

        unsigned hy0 = iy * P1;
        unsigned hy1 = hy0 + P1;
        unsigned hz0 = iz * P2;
        unsigned hz1 = hz0 + P2;
        unsigned r00 = hy0 ^ hz0;
        unsigned r10 = hy1 ^ hz0;
        unsigned r01 = hy0 ^ hz1;
        unsigned r11 = hy1 ^ hz1;

        const float2* tab = g_tables + (l << 15);
        float2 a00, b00, a10, b10, a01, b01, a11, b11;

        if ((ix & 1u) == 0u) {
            const float4* tab4 = reinterpret_cast<const float4*>(tab);
#define LOAD_PAIR(RYZ, AV, BV)                                              \
            {                                                               \
                unsigned i0 = (ix ^ (RYZ)) & HASH_MASK;                     \
                float4 q = __ldg(&tab4[i0 >> 1]);                           \
                float2 qlo = make_float2(q.x, q.y);                         \
                float2 qhi = make_float2(q.z, q.w);                         \
                bool sw = (i0 & 1u) != 0u;                                  \
                AV = sw ? qhi : qlo;                                        \
                BV = sw ? qlo : qhi;                                        \
            }
            LOAD_PAIR(r00, a00, b00)
            LOAD_PAIR(r10, a10, b10)
            LOAD_PAIR(r01, a01, b01)
            LOAD_PAIR(r11, a11, b11)
#undef LOAD_PAIR
        } else {
            unsigned x1 = ix + 1u;
            a00 = __ldg(&tab[(ix ^ r00) & HASH_MASK]);
            b00 = __ldg(&tab[(x1 ^ r00) & HASH_MASK]);
            a10 = __ldg(&tab[(ix ^ r10) & HASH_MASK]);
            b10 = __ldg(&tab[(x1 ^ r10) & HASH_MASK]);
            a01 = __ldg(&tab[(ix ^ r01) & HASH_MASK]);
            b01 = __ldg(&tab[(x1 ^ r01) & HASH_MASK]);
            a11 = __ldg(&tab[(ix ^ r11) & HASH_MASK]);
            b11 = __ldg(&tab[(x1 ^ r11) & HASH_MASK]);
        }

        float2 m00 = lerp2(a00, b00, wx);
        float2 m10 = lerp2(a10, b10, wx);
        float2 m01 = lerp2(a01, b01, wx);
        float2 m11 = lerp2(a11, b11, wx);
        float2 mm0 = lerp2(m00, m10, wy);
        float2 mm1 = lerp2(m01, m11, wy);
        float2 rr  = lerp2(mm0, mm1, wz);

        if ((k & 1) == 0) {
            prev = rr;
        } else {
            o[k >> 1] = make_float4(prev.x, prev.y, rr.x, rr.y);
        }
    }
}

// ---------------------------------------------------------------------------
// Launch
// ---------------------------------------------------------------------------
extern "C" void kernel_launch(void* const* d_in, const int* in_sizes, int n_in,
                              void* d_out, int out_size) {
    const float* x = (const float*)d_in[0];        // [524288, 3]
    const float* A = (const float*)d_in[1];        // [16, 32768, 4]
    const float* B = (const float*)d_in[2];        // [16, 4, 2]
    float* out = (float*)d_out;                    // [524288, 32]

    // Replicate numpy's resolution computation bit-exactly.
    ResParams p;
    double b = exp((log(512.0) - log(16.0)) / 15.0);
    for (int l = 0; l < N_LEVELS; l++) {
        double bl;
        if (l == 0)      bl = 1.0;
        else if (l == 1) bl = b;
        else if (l == 2) bl = b * b;
        else             bl = pow(b, (double)l);
        p.res[l] = (float)floor(16.0 * bl);
    }

    build_tables_kernel<<<(N_LEVELS * HASHMAP_SIZE) / 256, 256>>>(A, B);
    zero_hist_kernel<<<NBUCK / 1024, 256>>>();
    hist_kernel<<<NPTS / 256, 256>>>(x);
    scanA_kernel<<<256, 256>>>();
    scanB_kernel<<<1, 256>>>();
    scatter_kernel<<<NPTS / 256, 256>>>(x);
    encode_kernel<<<(2 * NPTS) / 256, 256>>>(out, p);
}

// round 9
// speedup vs baseline: 1.0999x; 1.0068x over previous
#include <cuda_runtime.h>
#include <math.h>

#define N_LEVELS 16
#define HASHMAP_SIZE 32768
#define HASH_MASK 32767u
#define NPTS 524288
#define P1 2654435761u
#define P2 805459861u
#define MBITS 6                       // morton bits per dim
#define NBUCK (1 << (3 * MBITS))      // 262144 buckets

// Materialized per-level tables: [16][32768] x float2 (4 MB), 16B-aligned.
__device__ __align__(16) float2 g_tables[N_LEVELS * HASHMAP_SIZE];

// Counting-sort scratch
__device__ __align__(16) unsigned g_hist[NBUCK];
__device__ __align__(16) unsigned g_offs[NBUCK];
__device__ unsigned g_blk[256];
__device__ float4   g_sx[NPTS];       // sorted normalized coords
__device__ int      g_sidx[NPTS];     // sorted slot -> original point index

struct ResParams { float res[N_LEVELS]; };

// ---------------------------------------------------------------------------
// Morton helpers
// ---------------------------------------------------------------------------
__device__ __forceinline__ unsigned part1by2(unsigned v) {
    v &= 0x3FFu;
    v = (v | (v << 16)) & 0x030000FFu;
    v = (v | (v << 8))  & 0x0300F00Fu;
    v = (v | (v << 4))  & 0x030C30C3u;
    v = (v | (v << 2))  & 0x09249249u;
    return v;
}

__device__ __forceinline__ unsigned morton_code(float xn0, float xn1, float xn2) {
    int cx = min(max((int)(xn0 * 64.0f), 0), 63);
    int cy = min(max((int)(xn1 * 64.0f), 0), 63);
    int cz = min(max((int)(xn2 * 64.0f), 0), 63);
    return part1by2((unsigned)cx)
         | (part1by2((unsigned)cy) << 1)
         | (part1by2((unsigned)cz) << 2);
}

// ---------------------------------------------------------------------------
// Kernel 1: build tables + zero hist (fused).
// ---------------------------------------------------------------------------
__global__ void __launch_bounds__(256) build_tables_kernel(
    const float* __restrict__ A, const float* __restrict__ B) {
    int idx = blockIdx.x * blockDim.x + threadIdx.x;   // 0 .. 524287
    if (idx < NBUCK / 4)
        reinterpret_cast<uint4*>(g_hist)[idx] = make_uint4(0u, 0u, 0u, 0u);

    int l = idx >> 15;
    float4 a = __ldg(reinterpret_cast<const float4*>(A) + idx);
    const float* b = B + l * 8;
    float f0 = a.x * b[0];
    f0 = fmaf(a.y, b[2], f0);
    f0 = fmaf(a.z, b[4], f0);
    f0 = fmaf(a.w, b[6], f0);
    float f1 = a.x * b[1];
    f1 = fmaf(a.y, b[3], f1);
    f1 = fmaf(a.z, b[5], f1);
    f1 = fmaf(a.w, b[7], f1);
    g_tables[idx] = make_float2(f0, f1);
}

__global__ void __launch_bounds__(256) hist_kernel(const float* __restrict__ x) {
    int n = blockIdx.x * blockDim.x + threadIdx.x;
    float xn0 = (__ldg(&x[3 * n + 0]) + 1.0f) * 0.5f;
    float xn1 = (__ldg(&x[3 * n + 1]) + 1.0f) * 0.5f;
    float xn2 = (__ldg(&x[3 * n + 2]) + 1.0f) * 0.5f;
    atomicAdd(&g_hist[morton_code(xn0, xn1, xn2)], 1u);
}

__global__ void __launch_bounds__(256) scanA_kernel() {
    __shared__ unsigned s[256];
    int t = threadIdx.x;
    int base = blockIdx.x * 1024 + t * 4;
    uint4 v = reinterpret_cast<const uint4*>(g_hist)[base >> 2];
    unsigned sum = v.x + v.y + v.z + v.w;
    s[t] = sum;
    __syncthreads();
#pragma unroll
    for (int d = 1; d < 256; d <<= 1) {
        unsigned u = (t >= d) ? s[t - d] : 0u;
        __syncthreads();
        s[t] += u;
        __syncthreads();
    }
    unsigned ex = s[t] - sum;
    uint4 o;
    o.x = ex;
    o.y = ex + v.x;
    o.z = o.y + v.y;
    o.w = o.z + v.z;
    reinterpret_cast<uint4*>(g_offs)[base >> 2] = o;
    if (t == 255) g_blk[blockIdx.x] = s[255];
}

__global__ void __launch_bounds__(256) scanB_kernel() {
    __shared__ unsigned s[256];
    int t = threadIdx.x;
    unsigned v = g_blk[t];
    s[t] = v;
    __syncthreads();
#pragma unroll
    for (int d = 1; d < 256; d <<= 1) {
        unsigned u = (t >= d) ? s[t - d] : 0u;
        __syncthreads();
        s[t] += u;
        __syncthreads();
    }
    g_blk[t] = s[t] - v;        // exclusive
}

// scatter: recomputes morton code (no g_bucket), fused block-offset add
__global__ void __launch_bounds__(256) scatter_kernel(const float* __restrict__ x) {
    int n = blockIdx.x * blockDim.x + threadIdx.x;
    float xn0 = (__ldg(&x[3 * n + 0]) + 1.0f) * 0.5f;
    float xn1 = (__ldg(&x[3 * n + 1]) + 1.0f) * 0.5f;
    float xn2 = (__ldg(&x[3 * n + 2]) + 1.0f) * 0.5f;
    unsigned code = morton_code(xn0, xn1, xn2);
    unsigned pos = atomicAdd(&g_offs[code], 1u) + __ldg(&g_blk[code >> 10]);
    g_sx[pos] = make_float4(xn0, xn1, xn2, 0.0f);
    g_sidx[pos] = n;
}

// ---------------------------------------------------------------------------
// Encode: thread = (sorted slot, half of levels), mixed halves within a warp.
// ---------------------------------------------------------------------------
__device__ __forceinline__ float2 lerp2(float2 a, float2 b, float t) {
    return make_float2(fmaf(t, b.x - a.x, a.x),
                       fmaf(t, b.y - a.y, a.y));
}

__global__ void __launch_bounds__(256) encode_kernel(
    float* __restrict__ out, ResParams p) {
    int tid = blockIdx.x * blockDim.x + threadIdx.x;   // 0 .. 2*NPTS-1
    int s    = tid >> 1;
    int half = tid & 1;
    int l0   = half << 3;

    float4 c = g_sx[s];
    int n = g_sidx[s];
    float xn0 = c.x, xn1 = c.y, xn2 = c.z;

    float4* o = reinterpret_cast<float4*>(out + (size_t)n * 32) + (half << 2);
    float2 prev;

#pragma unroll
    for (int k = 0; k < 8; k++) {
        int l = l0 + k;
        float r = p.res[l];
        float fx = xn0 * r, fy = xn1 * r, fz = xn2 * r;
        float flx = floorf(fx), fly = floorf(fy), flz = floorf(fz);
        float wx = fx - flx, wy = fy - fly, wz = fz - flz;
        unsigned ix = (unsigned)flx;
        unsigned iy = (unsigned)fly;
        unsigned iz = (unsigned)flz;

        unsigned hy0 = iy * P1;
        unsigned hy1 = hy0 + P1;
        unsigned hz0 = iz * P2;
        unsigned hz1 = hz0 + P2;
        unsigned r00 = hy0 ^ hz0;
        unsigned r10 = hy1 ^ hz0;
        unsigned r01 = hy0 ^ hz1;
        unsigned r11 = hy1 ^ hz1;

        const float2* tab = g_tables + (l << 15);
        float2 a00, b00, a10, b10, a01, b01, a11, b11;

        if ((ix & 1u) == 0u) {
            const float4* tab4 = reinterpret_cast<const float4*>(tab);
#define LOAD_PAIR(RYZ, AV, BV)                                              \
            {                                                               \
                unsigned i0 = (ix ^ (RYZ)) & HASH_MASK;                     \
                float4 q = __ldg(&tab4[i0 >> 1]);                           \
                float2 qlo = make_float2(q.x, q.y);                         \
                float2 qhi = make_float2(q.z, q.w);                         \
                bool sw = (i0 & 1u) != 0u;                                  \
                AV = sw ? qhi : qlo;                                        \
                BV = sw ? qlo : qhi;                                        \
            }
            LOAD_PAIR(r00, a00, b00)
            LOAD_PAIR(r10, a10, b10)
            LOAD_PAIR(r01, a01, b01)
            LOAD_PAIR(r11, a11, b11)
#undef LOAD_PAIR
        } else {
            unsigned x1 = ix + 1u;
            a00 = __ldg(&tab[(ix ^ r00) & HASH_MASK]);
            b00 = __ldg(&tab[(x1 ^ r00) & HASH_MASK]);
            a10 = __ldg(&tab[(ix ^ r10) & HASH_MASK]);
            b10 = __ldg(&tab[(x1 ^ r10) & HASH_MASK]);
            a01 = __ldg(&tab[(ix ^ r01) & HASH_MASK]);
            b01 = __ldg(&tab[(x1 ^ r01) & HASH_MASK]);
            a11 = __ldg(&tab[(ix ^ r11) & HASH_MASK]);
            b11 = __ldg(&tab[(x1 ^ r11) & HASH_MASK]);
        }

        float2 m00 = lerp2(a00, b00, wx);
        float2 m10 = lerp2(a10, b10, wx);
        float2 m01 = lerp2(a01, b01, wx);
        float2 m11 = lerp2(a11, b11, wx);
        float2 mm0 = lerp2(m00, m10, wy);
        float2 mm1 = lerp2(m01, m11, wy);
        float2 rr  = lerp2(mm0, mm1, wz);

        if ((k & 1) == 0) {
            prev = rr;
        } else {
            o[k >> 1] = make_float4(prev.x, prev.y, rr.x, rr.y);
        }
    }
}

// ---------------------------------------------------------------------------
// Launch
// ---------------------------------------------------------------------------
extern "C" void kernel_launch(void* const* d_in, const int* in_sizes, int n_in,
                              void* d_out, int out_size) {
    const float* x = (const float*)d_in[0];        // [524288, 3]
    const float* A = (const float*)d_in[1];        // [16, 32768, 4]
    const float* B = (const float*)d_in[2];        // [16, 4, 2]
    float* out = (float*)d_out;                    // [524288, 32]

    // Replicate numpy's resolution computation bit-exactly.
    ResParams p;
    double b = exp((log(512.0) - log(16.0)) / 15.0);
    for (int l = 0; l < N_LEVELS; l++) {
        double bl;
        if (l == 0)      bl = 1.0;
        else if (l == 1) bl = b;
        else if (l == 2) bl = b * b;
        else             bl = pow(b, (double)l);
        p.res[l] = (float)floor(16.0 * bl);
    }

    build_tables_kernel<<<(N_LEVELS * HASHMAP_SIZE) / 256, 256>>>(A, B);
    hist_kernel<<<NPTS / 256, 256>>>(x);
    scanA_kernel<<<256, 256>>>();
    scanB_kernel<<<1, 256>>>();
    scatter_kernel<<<NPTS / 256, 256>>>(x);
    encode_kernel<<<(2 * NPTS) / 256, 256>>>(out, p);
}

// round 10
// speedup vs baseline: 1.1329x; 1.0300x over previous
#include <cuda_runtime.h>
#include <math.h>

#define N_LEVELS 16
#define HASHMAP_SIZE 32768
#define HASH_MASK 32767u
#define NPTS 524288
#define P1 2654435761u
#define P2 805459861u
#define MBITS 6                       // morton bits per dim
#define NBUCK (1 << (3 * MBITS))      // 262144 buckets

// Materialized per-level tables: [16][32768] x float2 (4 MB), 16B-aligned.
__device__ __align__(16) float2 g_tables[N_LEVELS * HASHMAP_SIZE];

// Counting-sort scratch
__device__ __align__(16) unsigned g_hist[NBUCK];
__device__ __align__(16) unsigned g_offs[NBUCK];
__device__ unsigned g_total;
__device__ float4   g_sx[NPTS];   // sorted (xn0,xn1,xn2, bit-cast orig index)

struct ResParams { float res[N_LEVELS]; };

// ---------------------------------------------------------------------------
// Morton helpers
// ---------------------------------------------------------------------------
__device__ __forceinline__ unsigned part1by2(unsigned v) {
    v &= 0x3FFu;
    v = (v | (v << 16)) & 0x030000FFu;
    v = (v | (v << 8))  & 0x0300F00Fu;
    v = (v | (v << 4))  & 0x030C30C3u;
    v = (v | (v << 2))  & 0x09249249u;
    return v;
}

__device__ __forceinline__ unsigned morton_code(float xn0, float xn1, float xn2) {
    int cx = min(max((int)(xn0 * 64.0f), 0), 63);
    int cy = min(max((int)(xn1 * 64.0f), 0), 63);
    int cz = min(max((int)(xn2 * 64.0f), 0), 63);
    return part1by2((unsigned)cx)
         | (part1by2((unsigned)cy) << 1)
         | (part1by2((unsigned)cz) << 2);
}

// ---------------------------------------------------------------------------
// Kernel 1: build tables + zero hist & total (fused).
// ---------------------------------------------------------------------------
__global__ void __launch_bounds__(256) build_tables_kernel(
    const float* __restrict__ A, const float* __restrict__ B) {
    int idx = blockIdx.x * blockDim.x + threadIdx.x;   // 0 .. 524287
    if (idx < NBUCK / 4)
        reinterpret_cast<uint4*>(g_hist)[idx] = make_uint4(0u, 0u, 0u, 0u);
    if (idx == 0) g_total = 0u;

    int l = idx >> 15;
    float4 a = __ldg(reinterpret_cast<const float4*>(A) + idx);
    const float* b = B + l * 8;
    float f0 = a.x * b[0];
    f0 = fmaf(a.y, b[2], f0);
    f0 = fmaf(a.z, b[4], f0);
    f0 = fmaf(a.w, b[6], f0);
    float f1 = a.x * b[1];
    f1 = fmaf(a.y, b[3], f1);
    f1 = fmaf(a.z, b[5], f1);
    f1 = fmaf(a.w, b[7], f1);
    g_tables[idx] = make_float2(f0, f1);
}

__global__ void __launch_bounds__(256) hist_kernel(const float* __restrict__ x) {
    int n = blockIdx.x * blockDim.x + threadIdx.x;
    float xn0 = (__ldg(&x[3 * n + 0]) + 1.0f) * 0.5f;
    float xn1 = (__ldg(&x[3 * n + 1]) + 1.0f) * 0.5f;
    float xn2 = (__ldg(&x[3 * n + 2]) + 1.0f) * 0.5f;
    atomicAdd(&g_hist[morton_code(xn0, xn1, xn2)], 1u);
}

// ---------------------------------------------------------------------------
// Scan: per-block scan over 1024 hist entries; chunk base via atomicAdd on
// g_total (arrival-order chunk placement; within-chunk morton order kept).
// Writes FINAL bucket offsets to g_offs. No second scan kernel needed.
// ---------------------------------------------------------------------------
__global__ void __launch_bounds__(256) scan_kernel() {
    __shared__ unsigned s[256];
    __shared__ unsigned sbase;
    int t = threadIdx.x;
    int base4 = (blockIdx.x * 1024 + t * 4) >> 2;
    uint4 v = reinterpret_cast<const uint4*>(g_hist)[base4];
    unsigned sum = v.x + v.y + v.z + v.w;
    s[t] = sum;
    __syncthreads();
#pragma unroll
    for (int d = 1; d < 256; d <<= 1) {
        unsigned u = (t >= d) ? s[t - d] : 0u;
        __syncthreads();
        s[t] += u;
        __syncthreads();
    }
    if (t == 255) sbase = atomicAdd(&g_total, s[255]);
    unsigned ex = s[t] - sum;
    __syncthreads();
    unsigned base = sbase + ex;
    uint4 o;
    o.x = base;
    o.y = base + v.x;
    o.z = o.y + v.y;
    o.w = o.z + v.z;
    reinterpret_cast<uint4*>(g_offs)[base4] = o;
}

// scatter: recomputes morton code; index packed into g_sx.w
__global__ void __launch_bounds__(256) scatter_kernel(const float* __restrict__ x) {
    int n = blockIdx.x * blockDim.x + threadIdx.x;
    float xn0 = (__ldg(&x[3 * n + 0]) + 1.0f) * 0.5f;
    float xn1 = (__ldg(&x[3 * n + 1]) + 1.0f) * 0.5f;
    float xn2 = (__ldg(&x[3 * n + 2]) + 1.0f) * 0.5f;
    unsigned code = morton_code(xn0, xn1, xn2);
    unsigned pos = atomicAdd(&g_offs[code], 1u);
    g_sx[pos] = make_float4(xn0, xn1, xn2, __int_as_float(n));
}

// ---------------------------------------------------------------------------
// Encode: thread = (sorted slot, half of levels), mixed halves within a warp.
// ---------------------------------------------------------------------------
__device__ __forceinline__ float2 lerp2(float2 a, float2 b, float t) {
    return make_float2(fmaf(t, b.x - a.x, a.x),
                       fmaf(t, b.y - a.y, a.y));
}

__global__ void __launch_bounds__(256) encode_kernel(
    float* __restrict__ out, ResParams p) {
    int tid = blockIdx.x * blockDim.x + threadIdx.x;   // 0 .. 2*NPTS-1
    int s    = tid >> 1;
    int half = tid & 1;
    int l0   = half << 3;

    float4 c = g_sx[s];
    int n = __float_as_int(c.w);
    float xn0 = c.x, xn1 = c.y, xn2 = c.z;

    float4* o = reinterpret_cast<float4*>(out + (size_t)n * 32) + (half << 2);
    float2 prev;

#pragma unroll
    for (int k = 0; k < 8; k++) {
        int l = l0 + k;
        float r = p.res[l];
        float fx = xn0 * r, fy = xn1 * r, fz = xn2 * r;
        float flx = floorf(fx), fly = floorf(fy), flz = floorf(fz);
        float wx = fx - flx, wy = fy - fly, wz = fz - flz;
        unsigned ix = (unsigned)flx;
        unsigned iy = (unsigned)fly;
        unsigned iz = (unsigned)flz;

        unsigned hy0 = iy * P1;
        unsigned hy1 = hy0 + P1;
        unsigned hz0 = iz * P2;
        unsigned hz1 = hz0 + P2;
        unsigned r00 = hy0 ^ hz0;
        unsigned r10 = hy1 ^ hz0;
        unsigned r01 = hy0 ^ hz1;
        unsigned r11 = hy1 ^ hz1;

        const float2* tab = g_tables + (l << 15);
        float2 a00, b00, a10, b10, a01, b01, a11, b11;

        if ((ix & 1u) == 0u) {
            const float4* tab4 = reinterpret_cast<const float4*>(tab);
#define LOAD_PAIR(RYZ, AV, BV)                                              \
            {                                                               \
                unsigned i0 = (ix ^ (RYZ)) & HASH_MASK;                     \
                float4 q = __ldg(&tab4[i0 >> 1]);                           \
                float2 qlo = make_float2(q.x, q.y);                         \
                float2 qhi = make_float2(q.z, q.w);                         \
                bool sw = (i0 & 1u) != 0u;                                  \
                AV = sw ? qhi : qlo;                                        \
                BV = sw ? qlo : qhi;                                        \
            }
            LOAD_PAIR(r00, a00, b00)
            LOAD_PAIR(r10, a10, b10)
            LOAD_PAIR(r01, a01, b01)
            LOAD_PAIR(r11, a11, b11)
#undef LOAD_PAIR
        } else {
            unsigned x1 = ix + 1u;
            a00 = __ldg(&tab[(ix ^ r00) & HASH_MASK]);
            b00 = __ldg(&tab[(x1 ^ r00) & HASH_MASK]);
            a10 = __ldg(&tab[(ix ^ r10) & HASH_MASK]);
            b10 = __ldg(&tab[(x1 ^ r10) & HASH_MASK]);
            a01 = __ldg(&tab[(ix ^ r01) & HASH_MASK]);
            b01 = __ldg(&tab[(x1 ^ r01) & HASH_MASK]);
            a11 = __ldg(&tab[(ix ^ r11) & HASH_MASK]);
            b11 = __ldg(&tab[(x1 ^ r11) & HASH_MASK]);
        }

        float2 m00 = lerp2(a00, b00, wx);
        float2 m10 = lerp2(a10, b10, wx);
        float2 m01 = lerp2(a01, b01, wx);
        float2 m11 = lerp2(a11, b11, wx);
        float2 mm0 = lerp2(m00, m10, wy);
        float2 mm1 = lerp2(m01, m11, wy);
        float2 rr  = lerp2(mm0, mm1, wz);

        if ((k & 1) == 0) {
            prev = rr;
        } else {
            o[k >> 1] = make_float4(prev.x, prev.y, rr.x, rr.y);
        }
    }
}

// ---------------------------------------------------------------------------
// Launch
// ---------------------------------------------------------------------------
extern "C" void kernel_launch(void* const* d_in, const int* in_sizes, int n_in,
                              void* d_out, int out_size) {
    const float* x = (const float*)d_in[0];        // [524288, 3]
    const float* A = (const float*)d_in[1];        // [16, 32768, 4]
    const float* B = (const float*)d_in[2];        // [16, 4, 2]
    float* out = (float*)d_out;                    // [524288, 32]

    // Replicate numpy's resolution computation bit-exactly.
    ResParams p;
    double b = exp((log(512.0) - log(16.0)) / 15.0);
    for (int l = 0; l < N_LEVELS; l++) {
        double bl;
        if (l == 0)      bl = 1.0;
        else if (l == 1) bl = b;
        else if (l == 2) bl = b * b;
        else             bl = pow(b, (double)l);
        p.res[l] = (float)floor(16.0 * bl);
    }

    build_tables_kernel<<<(N_LEVELS * HASHMAP_SIZE) / 256, 256>>>(A, B);
    hist_kernel<<<NPTS / 256, 256>>>(x);
    scan_kernel<<<256, 256>>>();
    scatter_kernel<<<NPTS / 256, 256>>>(x);
    encode_kernel<<<(2 * NPTS) / 256, 256>>>(out, p);
}

// round 11
// speedup vs baseline: 1.1662x; 1.0294x over previous
#include <cuda_runtime.h>
#include <math.h>

#define N_LEVELS 16
#define HASHMAP_SIZE 32768
#define HASH_MASK 32767u
#define NPTS 524288
#define P1 2654435761u
#define P2 805459861u
#define MBITS 6                       // morton bits per dim
#define NBUCK (1 << (3 * MBITS))      // 262144 buckets

// Materialized per-level tables: [16][32768] x float2 (4 MB), 16B-aligned.
__device__ __align__(16) float2 g_tables[N_LEVELS * HASHMAP_SIZE];

// Counting-sort scratch
__device__ __align__(16) unsigned g_hist[NBUCK];
__device__ __align__(16) unsigned g_offs[NBUCK];
__device__ unsigned g_total;
__device__ float4   g_sx[NPTS];   // sorted (xn0,xn1,xn2, bit-cast orig index)

struct ResParams { float res[N_LEVELS]; };

// ---------------------------------------------------------------------------
// Morton helpers
// ---------------------------------------------------------------------------
__device__ __forceinline__ unsigned part1by2(unsigned v) {
    v &= 0x3FFu;
    v = (v | (v << 16)) & 0x030000FFu;
    v = (v | (v << 8))  & 0x0300F00Fu;
    v = (v | (v << 4))  & 0x030C30C3u;
    v = (v | (v << 2))  & 0x09249249u;
    return v;
}

__device__ __forceinline__ unsigned morton_code(float xn0, float xn1, float xn2) {
    int cx = min(max((int)(xn0 * 64.0f), 0), 63);
    int cy = min(max((int)(xn1 * 64.0f), 0), 63);
    int cz = min(max((int)(xn2 * 64.0f), 0), 63);
    return part1by2((unsigned)cx)
         | (part1by2((unsigned)cy) << 1)
         | (part1by2((unsigned)cz) << 2);
}

// ---------------------------------------------------------------------------
// Kernel 1 (fused): zero hist/total is NOT needed here because this kernel
// itself builds the histogram — instead we zero in a tiny preceding kernel?
// No: we zero g_hist inline FIRST is impossible (same kernel races).
// So: g_hist zeroing rides on a small dedicated kernel fused INTO scan? Also
// racy. Keep a separate tiny zero kernel? That re-adds a launch.
// Resolution: zero g_hist in the PREVIOUS graph replay's scan_kernel (it has
// the hist values loaded already and can reset them) + host-side first-launch
// is handled because __device__ globals are zero-initialized at module load,
// and scan_kernel re-zeros g_hist after consuming it every replay.
// g_total likewise reset by scan block 0 AFTER all blocks consumed it — not
// safe. Instead scatter's last action per point doesn't touch g_total; we
// reset g_total in build (no race: build doesn't read/write hist between
// zeroing and atomics? build DOES histogram). Order within build:
// g_total=0 is independent of hist atomics — safe (scan reads g_total only
// in the NEXT kernel).
// ---------------------------------------------------------------------------
__global__ void __launch_bounds__(256) build_hist_kernel(
    const float* __restrict__ A, const float* __restrict__ B,
    const float* __restrict__ x) {
    int idx = blockIdx.x * blockDim.x + threadIdx.x;   // 0 .. 524287
    if (idx == 0) g_total = 0u;

    // table build
    int l = idx >> 15;
    float4 a = __ldg(reinterpret_cast<const float4*>(A) + idx);
    const float* b = B + l * 8;
    float f0 = a.x * b[0];
    f0 = fmaf(a.y, b[2], f0);
    f0 = fmaf(a.z, b[4], f0);
    f0 = fmaf(a.w, b[6], f0);
    float f1 = a.x * b[1];
    f1 = fmaf(a.y, b[3], f1);
    f1 = fmaf(a.z, b[5], f1);
    f1 = fmaf(a.w, b[7], f1);
    g_tables[idx] = make_float2(f0, f1);

    // histogram (same thread count; independent role)
    float xn0 = (__ldg(&x[3 * idx + 0]) + 1.0f) * 0.5f;
    float xn1 = (__ldg(&x[3 * idx + 1]) + 1.0f) * 0.5f;
    float xn2 = (__ldg(&x[3 * idx + 2]) + 1.0f) * 0.5f;
    atomicAdd(&g_hist[morton_code(xn0, xn1, xn2)], 1u);
}

// ---------------------------------------------------------------------------
// Scan: per-block scan over 1024 hist entries; chunk base via atomicAdd on
// g_total. Writes FINAL bucket offsets to g_offs, then RE-ZEROS g_hist for
// the next graph replay (module-load init covers the very first launch).
// ---------------------------------------------------------------------------
__global__ void __launch_bounds__(256) scan_kernel() {
    __shared__ unsigned s[256];
    __shared__ unsigned sbase;
    int t = threadIdx.x;
    int base4 = (blockIdx.x * 1024 + t * 4) >> 2;
    uint4 v = reinterpret_cast<const uint4*>(g_hist)[base4];
    unsigned sum = v.x + v.y + v.z + v.w;
    s[t] = sum;
    __syncthreads();
#pragma unroll
    for (int d = 1; d < 256; d <<= 1) {
        unsigned u = (t >= d) ? s[t - d] : 0u;
        __syncthreads();
        s[t] += u;
        __syncthreads();
    }
    if (t == 255) sbase = atomicAdd(&g_total, s[255]);
    unsigned ex = s[t] - sum;
    __syncthreads();
    unsigned base = sbase + ex;
    uint4 o;
    o.x = base;
    o.y = base + v.x;
    o.z = o.y + v.y;
    o.w = o.z + v.z;
    reinterpret_cast<uint4*>(g_offs)[base4] = o;
    // reset hist for next replay (we already consumed it)
    reinterpret_cast<uint4*>(g_hist)[base4] = make_uint4(0u, 0u, 0u, 0u);
}

// ---------------------------------------------------------------------------
// Scatter: 4 points per thread for ILP on the atomic+scattered-store chain.
// ---------------------------------------------------------------------------
__global__ void __launch_bounds__(256) scatter_kernel(const float* __restrict__ x) {
    int t = blockIdx.x * blockDim.x + threadIdx.x;   // 0 .. NPTS/4-1
    const float4* xv = reinterpret_cast<const float4*>(x) + 3 * (size_t)t;
    float4 v0 = __ldg(&xv[0]);
    float4 v1 = __ldg(&xv[1]);
    float4 v2 = __ldg(&xv[2]);
    float px[12] = { v0.x, v0.y, v0.z, v0.w,
                     v1.x, v1.y, v1.z, v1.w,
                     v2.x, v2.y, v2.z, v2.w };
    int n0 = 4 * t;
#pragma unroll
    for (int k = 0; k < 4; k++) {
        float xn0 = (px[3 * k + 0] + 1.0f) * 0.5f;
        float xn1 = (px[3 * k + 1] + 1.0f) * 0.5f;
        float xn2 = (px[3 * k + 2] + 1.0f) * 0.5f;
        unsigned code = morton_code(xn0, xn1, xn2);
        unsigned pos = atomicAdd(&g_offs[code], 1u);
        g_sx[pos] = make_float4(xn0, xn1, xn2, __int_as_float(n0 + k));
    }
}

// ---------------------------------------------------------------------------
// Encode: thread = (sorted slot, half of levels), mixed halves within a warp.
// ---------------------------------------------------------------------------
__device__ __forceinline__ float2 lerp2(float2 a, float2 b, float t) {
    return make_float2(fmaf(t, b.x - a.x, a.x),
                       fmaf(t, b.y - a.y, a.y));
}

__global__ void __launch_bounds__(256) encode_kernel(
    float* __restrict__ out, ResParams p) {
    int tid = blockIdx.x * blockDim.x + threadIdx.x;   // 0 .. 2*NPTS-1
    int s    = tid >> 1;
    int half = tid & 1;
    int l0   = half << 3;

    float4 c = g_sx[s];
    int n = __float_as_int(c.w);
    float xn0 = c.x, xn1 = c.y, xn2 = c.z;

    float4* o = reinterpret_cast<float4*>(out + (size_t)n * 32) + (half << 2);
    float2 prev;

#pragma unroll
    for (int k = 0; k < 8; k++) {
        int l = l0 + k;
        float r = p.res[l];
        float fx = xn0 * r, fy = xn1 * r, fz = xn2 * r;
        float flx = floorf(fx), fly = floorf(fy), flz = floorf(fz);
        float wx = fx - flx, wy = fy - fly, wz = fz - flz;
        unsigned ix = (unsigned)flx;
        unsigned iy = (unsigned)fly;
        unsigned iz = (unsigned)flz;

        unsigned hy0 = iy * P1;
        unsigned hy1 = hy0 + P1;
        unsigned hz0 = iz * P2;
        unsigned hz1 = hz0 + P2;
        unsigned r00 = hy0 ^ hz0;
        unsigned r10 = hy1 ^ hz0;
        unsigned r01 = hy0 ^ hz1;
        unsigned r11 = hy1 ^ hz1;

        const float2* tab = g_tables + (l << 15);
        float2 a00, b00, a10, b10, a01, b01, a11, b11;

        if ((ix & 1u) == 0u) {
            const float4* tab4 = reinterpret_cast<const float4*>(tab);
#define LOAD_PAIR(RYZ, AV, BV)                                              \
            {                                                               \
                unsigned i0 = (ix ^ (RYZ)) & HASH_MASK;                     \
                float4 q = __ldg(&tab4[i0 >> 1]);                           \
                float2 qlo = make_float2(q.x, q.y);                         \
                float2 qhi = make_float2(q.z, q.w);                         \
                bool sw = (i0 & 1u) != 0u;                                  \
                AV = sw ? qhi : qlo;                                        \
                BV = sw ? qlo : qhi;                                        \
            }
            LOAD_PAIR(r00, a00, b00)
            LOAD_PAIR(r10, a10, b10)
            LOAD_PAIR(r01, a01, b01)
            LOAD_PAIR(r11, a11, b11)
#undef LOAD_PAIR
        } else {
            unsigned x1 = ix + 1u;
            a00 = __ldg(&tab[(ix ^ r00) & HASH_MASK]);
            b00 = __ldg(&tab[(x1 ^ r00) & HASH_MASK]);
            a10 = __ldg(&tab[(ix ^ r10) & HASH_MASK]);
            b10 = __ldg(&tab[(x1 ^ r10) & HASH_MASK]);
            a01 = __ldg(&tab[(ix ^ r01) & HASH_MASK]);
            b01 = __ldg(&tab[(x1 ^ r01) & HASH_MASK]);
            a11 = __ldg(&tab[(ix ^ r11) & HASH_MASK]);
            b11 = __ldg(&tab[(x1 ^ r11) & HASH_MASK]);
        }

        float2 m00 = lerp2(a00, b00, wx);
        float2 m10 = lerp2(a10, b10, wx);
        float2 m01 = lerp2(a01, b01, wx);
        float2 m11 = lerp2(a11, b11, wx);
        float2 mm0 = lerp2(m00, m10, wy);
        float2 mm1 = lerp2(m01, m11, wy);
        float2 rr  = lerp2(mm0, mm1, wz);

        if ((k & 1) == 0) {
            prev = rr;
        } else {
            o[k >> 1] = make_float4(prev.x, prev.y, rr.x, rr.y);
        }
    }
}

// ---------------------------------------------------------------------------
// Launch
// ---------------------------------------------------------------------------
extern "C" void kernel_launch(void* const* d_in, const int* in_sizes, int n_in,
                              void* d_out, int out_size) {
    const float* x = (const float*)d_in[0];        // [524288, 3]
    const float* A = (const float*)d_in[1];        // [16, 32768, 4]
    const float* B = (const float*)d_in[2];        // [16, 4, 2]
    float* out = (float*)d_out;                    // [524288, 32]

    // Replicate numpy's resolution computation bit-exactly.
    ResParams p;
    double b = exp((log(512.0) - log(16.0)) / 15.0);
    for (int l = 0; l < N_LEVELS; l++) {
        double bl;
        if (l == 0)      bl = 1.0;
        else if (l == 1) bl = b;
        else if (l == 2) bl = b * b;
        else             bl = pow(b, (double)l);
        p.res[l] = (float)floor(16.0 * bl);
    }

    build_hist_kernel<<<NPTS / 256, 256>>>(A, B, x);
    scan_kernel<<<256, 256>>>();
    scatter_kernel<<<(NPTS / 4) / 256, 256>>>(x);
    encode_kernel<<<(2 * NPTS) / 256, 256>>>(out, p);
}

// round 12
// speedup vs baseline: 1.2097x; 1.0373x over previous
#include <cuda_runtime.h>
#include <math.h>

#define N_LEVELS 16
#define HASHMAP_SIZE 32768
#define HASH_MASK 32767u
#define NPTS 524288
#define P1 2654435761u
#define P2 805459861u
#define MBITS 6                       // morton bits per dim
#define NBUCK (1 << (3 * MBITS))      // 262144 buckets

// Materialized per-level tables: [16][32768] x float2 (4 MB), 16B-aligned.
__device__ __align__(16) float2 g_tables[N_LEVELS * HASHMAP_SIZE];

// Counting-sort scratch
__device__ __align__(16) unsigned g_hist[NBUCK];
__device__ __align__(16) unsigned g_offs[NBUCK];
__device__ unsigned g_total;
__device__ float4   g_sx[NPTS];   // sorted (xn0,xn1,xn2, bit-cast orig index)

struct ResParams { float res[N_LEVELS]; };

// ---------------------------------------------------------------------------
// Morton helpers
// ---------------------------------------------------------------------------
__device__ __forceinline__ unsigned part1by2(unsigned v) {
    v &= 0x3FFu;
    v = (v | (v << 16)) & 0x030000FFu;
    v = (v | (v << 8))  & 0x0300F00Fu;
    v = (v | (v << 4))  & 0x030C30C3u;
    v = (v | (v << 2))  & 0x09249249u;
    return v;
}

__device__ __forceinline__ unsigned morton_code(float xn0, float xn1, float xn2) {
    int cx = min(max((int)(xn0 * 64.0f), 0), 63);
    int cy = min(max((int)(xn1 * 64.0f), 0), 63);
    int cz = min(max((int)(xn2 * 64.0f), 0), 63);
    return part1by2((unsigned)cx)
         | (part1by2((unsigned)cy) << 1)
         | (part1by2((unsigned)cz) << 2);
}

// ---------------------------------------------------------------------------
// Kernel 1 (fused): table build + point histogram. g_hist is re-zeroed by
// scan_kernel each replay (module-load zero-init covers the first launch).
// ---------------------------------------------------------------------------
__global__ void __launch_bounds__(256) build_hist_kernel(
    const float* __restrict__ A, const float* __restrict__ B,
    const float* __restrict__ x) {
    int idx = blockIdx.x * blockDim.x + threadIdx.x;   // 0 .. 524287
    if (idx == 0) g_total = 0u;

    int l = idx >> 15;
    float4 a = __ldg(reinterpret_cast<const float4*>(A) + idx);
    const float* b = B + l * 8;
    float f0 = a.x * b[0];
    f0 = fmaf(a.y, b[2], f0);
    f0 = fmaf(a.z, b[4], f0);
    f0 = fmaf(a.w, b[6], f0);
    float f1 = a.x * b[1];
    f1 = fmaf(a.y, b[3], f1);
    f1 = fmaf(a.z, b[5], f1);
    f1 = fmaf(a.w, b[7], f1);
    g_tables[idx] = make_float2(f0, f1);

    float xn0 = (__ldg(&x[3 * idx + 0]) + 1.0f) * 0.5f;
    float xn1 = (__ldg(&x[3 * idx + 1]) + 1.0f) * 0.5f;
    float xn2 = (__ldg(&x[3 * idx + 2]) + 1.0f) * 0.5f;
    atomicAdd(&g_hist[morton_code(xn0, xn1, xn2)], 1u);
}

// ---------------------------------------------------------------------------
// Scan: per-block scan; chunk base via atomicAdd on g_total. Re-zeros g_hist.
// ---------------------------------------------------------------------------
__global__ void __launch_bounds__(256) scan_kernel() {
    __shared__ unsigned s[256];
    __shared__ unsigned sbase;
    int t = threadIdx.x;
    int base4 = (blockIdx.x * 1024 + t * 4) >> 2;
    uint4 v = reinterpret_cast<const uint4*>(g_hist)[base4];
    unsigned sum = v.x + v.y + v.z + v.w;
    s[t] = sum;
    __syncthreads();
#pragma unroll
    for (int d = 1; d < 256; d <<= 1) {
        unsigned u = (t >= d) ? s[t - d] : 0u;
        __syncthreads();
        s[t] += u;
        __syncthreads();
    }
    if (t == 255) sbase = atomicAdd(&g_total, s[255]);
    unsigned ex = s[t] - sum;
    __syncthreads();
    unsigned base = sbase + ex;
    uint4 o;
    o.x = base;
    o.y = base + v.x;
    o.z = o.y + v.y;
    o.w = o.z + v.z;
    reinterpret_cast<uint4*>(g_offs)[base4] = o;
    reinterpret_cast<uint4*>(g_hist)[base4] = make_uint4(0u, 0u, 0u, 0u);
}

// ---------------------------------------------------------------------------
// Scatter: 4 points per thread for ILP on the atomic+scattered-store chain.
// ---------------------------------------------------------------------------
__global__ void __launch_bounds__(256) scatter_kernel(const float* __restrict__ x) {
    int t = blockIdx.x * blockDim.x + threadIdx.x;   // 0 .. NPTS/4-1
    const float4* xv = reinterpret_cast<const float4*>(x) + 3 * (size_t)t;
    float4 v0 = __ldg(&xv[0]);
    float4 v1 = __ldg(&xv[1]);
    float4 v2 = __ldg(&xv[2]);
    float px[12] = { v0.x, v0.y, v0.z, v0.w,
                     v1.x, v1.y, v1.z, v1.w,
                     v2.x, v2.y, v2.z, v2.w };
    int n0 = 4 * t;
#pragma unroll
    for (int k = 0; k < 4; k++) {
        float xn0 = (px[3 * k + 0] + 1.0f) * 0.5f;
        float xn1 = (px[3 * k + 1] + 1.0f) * 0.5f;
        float xn2 = (px[3 * k + 2] + 1.0f) * 0.5f;
        unsigned code = morton_code(xn0, xn1, xn2);
        unsigned pos = atomicAdd(&g_offs[code], 1u);
        g_sx[pos] = make_float4(xn0, xn1, xn2, __int_as_float(n0 + k));
    }
}

// ---------------------------------------------------------------------------
// Encode: thread = (sorted slot, half of levels), mixed halves within a warp.
// Even-x path uses weight-flip instead of value swap: keep the float4 as
// (qlo, qhi) and lerp with wp = (i0&1) ? 1-wx : wx  (1 select vs 4).
// ---------------------------------------------------------------------------
__device__ __forceinline__ float2 lerp2(float2 a, float2 b, float t) {
    return make_float2(fmaf(t, b.x - a.x, a.x),
                       fmaf(t, b.y - a.y, a.y));
}

__global__ void __launch_bounds__(256) encode_kernel(
    float* __restrict__ out, ResParams p) {
    int tid = blockIdx.x * blockDim.x + threadIdx.x;   // 0 .. 2*NPTS-1
    int s    = tid >> 1;
    int half = tid & 1;
    int l0   = half << 3;

    float4 c = g_sx[s];
    int n = __float_as_int(c.w);
    float xn0 = c.x, xn1 = c.y, xn2 = c.z;

    float4* o = reinterpret_cast<float4*>(out + (size_t)n * 32) + (half << 2);
    float2 prev;

#pragma unroll
    for (int k = 0; k < 8; k++) {
        int l = l0 + k;
        float r = p.res[l];
        float fx = xn0 * r, fy = xn1 * r, fz = xn2 * r;
        float flx = floorf(fx), fly = floorf(fy), flz = floorf(fz);
        float wx = fx - flx, wy = fy - fly, wz = fz - flz;
        unsigned ix = (unsigned)flx;
        unsigned iy = (unsigned)fly;
        unsigned iz = (unsigned)flz;

        unsigned hy0 = iy * P1;
        unsigned hy1 = hy0 + P1;
        unsigned hz0 = iz * P2;
        unsigned hz1 = hz0 + P2;
        unsigned r00 = hy0 ^ hz0;
        unsigned r10 = hy1 ^ hz0;
        unsigned r01 = hy0 ^ hz1;
        unsigned r11 = hy1 ^ hz1;

        const float2* tab = g_tables + (l << 15);
        float2 m00, m10, m01, m11;

        if ((ix & 1u) == 0u) {
            const float4* tab4 = reinterpret_cast<const float4*>(tab);
            float wxc = 1.0f - wx;
#define XLERP(RYZ, M)                                                       \
            {                                                               \
                unsigned i0 = (ix ^ (RYZ)) & HASH_MASK;                     \
                float4 q = __ldg(&tab4[i0 >> 1]);                           \
                float wp = (i0 & 1u) ? wxc : wx;                            \
                M = make_float2(fmaf(wp, q.z - q.x, q.x),                   \
                                fmaf(wp, q.w - q.y, q.y));                  \
            }
            XLERP(r00, m00)
            XLERP(r10, m10)
            XLERP(r01, m01)
            XLERP(r11, m11)
#undef XLERP
        } else {
            unsigned x1 = ix + 1u;
            float2 a00 = __ldg(&tab[(ix ^ r00) & HASH_MASK]);
            float2 b00 = __ldg(&tab[(x1 ^ r00) & HASH_MASK]);
            float2 a10 = __ldg(&tab[(ix ^ r10) & HASH_MASK]);
            float2 b10 = __ldg(&tab[(x1 ^ r10) & HASH_MASK]);
            float2 a01 = __ldg(&tab[(ix ^ r01) & HASH_MASK]);
            float2 b01 = __ldg(&tab[(x1 ^ r01) & HASH_MASK]);
            float2 a11 = __ldg(&tab[(ix ^ r11) & HASH_MASK]);
            float2 b11 = __ldg(&tab[(x1 ^ r11) & HASH_MASK]);
            m00 = lerp2(a00, b00, wx);
            m10 = lerp2(a10, b10, wx);
            m01 = lerp2(a01, b01, wx);
            m11 = lerp2(a11, b11, wx);
        }

        float2 mm0 = lerp2(m00, m10, wy);
        float2 mm1 = lerp2(m01, m11, wy);
        float2 rr  = lerp2(mm0, mm1, wz);

        if ((k & 1) == 0) {
            prev = rr;
        } else {
            o[k >> 1] = make_float4(prev.x, prev.y, rr.x, rr.y);
        }
    }
}

// ---------------------------------------------------------------------------
// Launch
// ---------------------------------------------------------------------------
extern "C" void kernel_launch(void* const* d_in, const int* in_sizes, int n_in,
                              void* d_out, int out_size) {
    const float* x = (const float*)d_in[0];        // [524288, 3]
    const float* A = (const float*)d_in[1];        // [16, 32768, 4]
    const float* B = (const float*)d_in[2];        // [16, 4, 2]
    float* out = (float*)d_out;                    // [524288, 32]

    // Replicate numpy's resolution computation bit-exactly.
    ResParams p;
    double b = exp((log(512.0) - log(16.0)) / 15.0);
    for (int l = 0; l < N_LEVELS; l++) {
        double bl;
        if (l == 0)      bl = 1.0;
        else if (l == 1) bl = b;
        else if (l == 2) bl = b * b;
        else             bl = pow(b, (double)l);
        p.res[l] = (float)floor(16.0 * bl);
    }

    build_hist_kernel<<<NPTS / 256, 256>>>(A, B, x);
    scan_kernel<<<256, 256>>>();
    scatter_kernel<<<(NPTS / 4) / 256, 256>>>(x);
    encode_kernel<<<(2 * NPTS) / 256, 256>>>(out, p);
}